// round 1
// baseline (speedup 1.0000x reference)
#include <cuda_runtime.h>
#include <cstdint>

#define P_    8
#define T_    2048
#define N_    8192
#define M_    20000
#define DLAT  1024
#define DFEAT 512
#define DIN   1536      // DLAT + DFEAT
#define MSPLIT 8
#define MCHUNK 2500     // 20000 / 8

// ---------------- scratch (no runtime allocation allowed) ----------------
__device__ float g_part_d[N_ * MSPLIT];
__device__ int   g_part_i[N_ * MSPLIT];
__device__ int   g_nearest[N_];                       // argmin into M for each of 8192 obj pts
__device__ int   g_fidx[2 * P_ * T_];                 // [which][p][t] -> index into precomputed_feats
__device__ float g_gfeats[2L * P_ * T_ * DFEAT];      // gathered feature rows (64 MB)

// ---------------- kernel 1: obj_pts[0] vs precomputed_points (partial argmin) ----------------
// grid (8192/128, MSPLIT), block 128. Each block: 128 queries x one 2500-candidate chunk.
__global__ void nn1_partial(const float* __restrict__ os, const float* __restrict__ pts) {
    __shared__ float4 sP[MCHUNK];
    const int ms = blockIdx.y;
    const int m0 = ms * MCHUNK;
    for (int i = threadIdx.x; i < MCHUNK; i += 128) {
        float x = pts[(size_t)(m0 + i) * 3 + 0];
        float y = pts[(size_t)(m0 + i) * 3 + 1];
        float z = pts[(size_t)(m0 + i) * 3 + 2];
        sP[i] = make_float4(x, y, z, x * x + y * y + z * z);
    }
    __syncthreads();
    const int q = blockIdx.x * 128 + threadIdx.x;
    const float qx = -2.0f * os[(size_t)q * 6 + 0];
    const float qy = -2.0f * os[(size_t)q * 6 + 1];
    const float qz = -2.0f * os[(size_t)q * 6 + 2];
    float best = 3.4e38f;
    int bi = 0;
    #pragma unroll 5
    for (int i = 0; i < MCHUNK; i++) {
        float4 c = sP[i];
        float d = fmaf(qx, c.x, fmaf(qy, c.y, fmaf(qz, c.z, c.w)));
        if (d < best) { best = d; bi = i; }
    }
    g_part_d[q * MSPLIT + ms] = best;
    g_part_i[q * MSPLIT + ms] = m0 + bi;
}

__global__ void nn1_reduce() {
    const int q = blockIdx.x * blockDim.x + threadIdx.x;
    float best = g_part_d[q * MSPLIT];
    int bi = g_part_i[q * MSPLIT];
    #pragma unroll
    for (int s = 1; s < MSPLIT; s++) {
        float d = g_part_d[q * MSPLIT + s];
        if (d < best) { best = d; bi = g_part_i[q * MSPLIT + s]; }
    }
    g_nearest[q] = bi;
}

// ---------------- kernel 2: local/global pc vs obj_pts[p], fused with nearest_idx lookup ----------------
// grid (T/256, P, 2), block 256. which: 0 = local (geo), 1 = global (obj).
__global__ void match_kernel(const float* __restrict__ os,
                             const float* __restrict__ local_pc,
                             const float* __restrict__ global_pc) {
    __shared__ float4 sP[2048];
    const int p = blockIdx.y;
    const int which = blockIdx.z;
    const float* qsrc = (which == 0) ? local_pc : global_pc;
    const int t = blockIdx.x * 256 + threadIdx.x;
    const size_t qb = ((size_t)p * T_ + t) * 3;
    const float qx = -2.0f * qsrc[qb + 0];
    const float qy = -2.0f * qsrc[qb + 1];
    const float qz = -2.0f * qsrc[qb + 2];
    float best = 3.4e38f;
    int bi = 0;
    for (int nt = 0; nt < N_; nt += 2048) {
        __syncthreads();
        for (int i = threadIdx.x; i < 2048; i += 256) {
            size_t b = ((size_t)p * N_ + nt + i) * 6;
            float x = os[b + 0], y = os[b + 1], z = os[b + 2];
            sP[i] = make_float4(x, y, z, x * x + y * y + z * z);
        }
        __syncthreads();
        #pragma unroll 8
        for (int i = 0; i < 2048; i++) {
            float4 c = sP[i];
            float d = fmaf(qx, c.x, fmaf(qy, c.y, fmaf(qz, c.z, c.w)));
            if (d < best) { best = d; bi = nt + i; }
        }
    }
    g_fidx[(size_t)which * (P_ * T_) + (size_t)p * T_ + t] = g_nearest[bi];
}

// ---------------- kernel 3: gather feature rows ----------------
// grid 2*P*T blocks, 128 threads: each block copies one 512-float row (as float4).
__global__ void gather_kernel(const float* __restrict__ pf) {
    const int row = blockIdx.x;
    const int fi = g_fidx[row];
    const float4* src = (const float4*)(pf + (size_t)fi * DFEAT);
    float4* dst = (float4*)(g_gfeats + (size_t)row * DFEAT);
    dst[threadIdx.x] = src[threadIdx.x];
}

// ---------------- kernel 4: GEMM  C[16384,1024] = [raw | gfeats] @ W[1536,1024] + bias ----------------
// BM=128, BN=128, BK=16, 256 threads, 8x8 per-thread micro-tile.
__global__ void __launch_bounds__(256, 2)
gemm_kernel(const float* __restrict__ Araw, int which,
            const float* __restrict__ W, const float* __restrict__ bias,
            float* __restrict__ C) {
    __shared__ float As[16][128];
    __shared__ float Bs[16][128];

    const float* Afeat = g_gfeats + (size_t)which * (P_ * T_) * DFEAT;
    const int n0 = blockIdx.x * 128;
    const int m0 = blockIdx.y * 128;
    const int tid = threadIdx.x;
    const int tx = tid & 15;
    const int ty = tid >> 4;

    float acc[8][8];
    #pragma unroll
    for (int i = 0; i < 8; i++)
        #pragma unroll
        for (int j = 0; j < 8; j++) acc[i][j] = 0.0f;

    for (int k0 = 0; k0 < DIN; k0 += 16) {
        // --- load A tile (transposed into As[k][m]) ---
        const float* Ab;
        int lda;
        if (k0 < DLAT) { Ab = Araw + (size_t)m0 * DLAT + k0; lda = DLAT; }
        else           { Ab = Afeat + (size_t)m0 * DFEAT + (k0 - DLAT); lda = DFEAT; }
        #pragma unroll
        for (int rep = 0; rep < 2; rep++) {
            int lin = rep * 256 + tid;
            int r = lin >> 2;
            int cq = (lin & 3) * 4;
            float4 v = *(const float4*)(Ab + (size_t)r * lda + cq);
            As[cq + 0][r] = v.x;
            As[cq + 1][r] = v.y;
            As[cq + 2][r] = v.z;
            As[cq + 3][r] = v.w;
        }
        // --- load B tile ---
        #pragma unroll
        for (int rep = 0; rep < 2; rep++) {
            int lin = rep * 256 + tid;
            int r = lin >> 5;
            int cq = (lin & 31) * 4;
            *(float4*)(&Bs[r][cq]) = *(const float4*)(W + (size_t)(k0 + r) * DLAT + n0 + cq);
        }
        __syncthreads();
        // --- compute ---
        #pragma unroll
        for (int k = 0; k < 16; k++) {
            float a[8], b[8];
            *(float4*)(a)     = *(const float4*)(&As[k][ty * 8]);
            *(float4*)(a + 4) = *(const float4*)(&As[k][ty * 8 + 4]);
            *(float4*)(b)     = *(const float4*)(&Bs[k][tx * 8]);
            *(float4*)(b + 4) = *(const float4*)(&Bs[k][tx * 8 + 4]);
            #pragma unroll
            for (int i = 0; i < 8; i++)
                #pragma unroll
                for (int j = 0; j < 8; j++)
                    acc[i][j] = fmaf(a[i], b[j], acc[i][j]);
        }
        __syncthreads();
    }

    // --- epilogue: + bias, store ---
    float bsv[8];
    *(float4*)(bsv)     = *(const float4*)(bias + n0 + tx * 8);
    *(float4*)(bsv + 4) = *(const float4*)(bias + n0 + tx * 8 + 4);
    #pragma unroll
    for (int i = 0; i < 8; i++) {
        const int m = m0 + ty * 8 + i;
        #pragma unroll
        for (int j = 0; j < 8; j += 4) {
            float4 v;
            v.x = acc[i][j + 0] + bsv[j + 0];
            v.y = acc[i][j + 1] + bsv[j + 1];
            v.z = acc[i][j + 2] + bsv[j + 2];
            v.w = acc[i][j + 3] + bsv[j + 3];
            *(float4*)(&C[(size_t)m * DLAT + n0 + tx * 8 + j]) = v;
        }
    }
}

// ---------------- launch ----------------
extern "C" void kernel_launch(void* const* d_in, const int* in_sizes, int n_in,
                              void* d_out, int out_size) {
    const float* object_surface = (const float*)d_in[0];   // (8, 8192, 6)
    const float* pre_pts        = (const float*)d_in[1];   // (20000, 3)
    const float* pre_feats      = (const float*)d_in[2];   // (20000, 512)
    const float* geo_raw        = (const float*)d_in[3];   // (8, 2048, 1024)
    const float* obj_raw        = (const float*)d_in[4];   // (8, 2048, 1024)
    const float* local_pc       = (const float*)d_in[5];   // (8, 2048, 3)
    const float* global_pc      = (const float*)d_in[6];   // (8, 2048, 3)
    const float* Wg             = (const float*)d_in[7];   // (1536, 1024)
    const float* bg             = (const float*)d_in[8];   // (1024,)
    const float* Wo             = (const float*)d_in[9];   // (1536, 1024)
    const float* bo             = (const float*)d_in[10];  // (1024,)
    float* out = (float*)d_out;                            // geo_cond then obj_cond

    // 1) nearest_idx: obj_pts[0] vs precomputed_points
    nn1_partial<<<dim3(N_ / 128, MSPLIT), 128>>>(object_surface, pre_pts);
    nn1_reduce<<<N_ / 256, 256>>>();

    // 2) l_match / g_match -> feature indices
    match_kernel<<<dim3(T_ / 256, P_, 2), 256>>>(object_surface, local_pc, global_pc);

    // 3) gather feature rows (which=0: geo/local, which=1: obj/global)
    gather_kernel<<<2 * P_ * T_, DFEAT / 4>>>(pre_feats);

    // 4) GEMMs: geo_cond first half of out, obj_cond second half
    dim3 ggrid(DLAT / 128, (P_ * T_) / 128);
    gemm_kernel<<<ggrid, 256>>>(geo_raw, 0, Wg, bg, out);
    gemm_kernel<<<ggrid, 256>>>(obj_raw, 1, Wo, bo, out + (size_t)P_ * T_ * DLAT);
}

// round 3
// speedup vs baseline: 2.4069x; 2.4069x over previous
#include <cuda_runtime.h>
#include <cuda_bf16.h>
#include <cstdint>

#define P_    8
#define T_    2048
#define N_    8192
#define M_    20000
#define DLAT  1024
#define DFEAT 512
#define DIN   1536
#define MSPLIT 8
#define MCHUNK 2500

// ---- GEMM config (mma.sync bf16, K' = 3*DIN via hi/lo split terms) ----
#define BM 128
#define BN 128
#define BK 64                    // bf16 k per stage
#define KPRIME (3 * DIN)         // 4608
#define NIT (KPRIME / BK)        // 72
#define NSTAGE 3
#define STAGE_BYTES 32768        // A 16K + B 16K
#define GEMM_SMEM (NSTAGE * STAGE_BYTES)   // 96KB

// ---------------- scratch ----------------
__device__ float g_part_d[N_ * MSPLIT];
__device__ int   g_part_i[N_ * MSPLIT];
__device__ int   g_nearest[N_];
__device__ int   g_fidx[2 * P_ * T_];
__device__ __nv_bfloat16 g_Ah[2L * P_ * T_ * DIN];   // [gemm][m][k] hi
__device__ __nv_bfloat16 g_Al[2L * P_ * T_ * DIN];   // [gemm][m][k] lo
__device__ __nv_bfloat16 g_Bh[2L * DLAT * DIN];      // [gemm][n][k] hi (W^T)
__device__ __nv_bfloat16 g_Bl[2L * DLAT * DIN];      // [gemm][n][k] lo

// ---------------- helpers ----------------
__device__ __forceinline__ uint32_t smem_u32(const void* p) {
    uint32_t a;
    asm("{ .reg .u64 t; cvta.to.shared.u64 t, %1; cvt.u32.u64 %0, t; }" : "=r"(a) : "l"(p));
    return a;
}
__device__ __forceinline__ void cp16(uint32_t dst, const void* src) {
    asm volatile("cp.async.cg.shared.global [%0], [%1], 16;" :: "r"(dst), "l"(src) : "memory");
}
#define CP_COMMIT() asm volatile("cp.async.commit_group;" ::: "memory")
#define CP_WAIT(n)  asm volatile("cp.async.wait_group %0;" :: "n"(n) : "memory")

__device__ __forceinline__ void ldmx4(uint32_t addr, uint32_t& r0, uint32_t& r1,
                                      uint32_t& r2, uint32_t& r3) {
    asm volatile("ldmatrix.sync.aligned.m8n8.x4.shared.b16 {%0,%1,%2,%3}, [%4];"
                 : "=r"(r0), "=r"(r1), "=r"(r2), "=r"(r3) : "r"(addr));
}
__device__ __forceinline__ void mma16816(float& c0, float& c1, float& c2, float& c3,
                                         uint32_t a0, uint32_t a1, uint32_t a2, uint32_t a3,
                                         uint32_t b0, uint32_t b1) {
    asm volatile("mma.sync.aligned.m16n8k16.row.col.f32.bf16.bf16.f32 "
                 "{%0,%1,%2,%3}, {%4,%5,%6,%7}, {%8,%9}, {%0,%1,%2,%3};"
                 : "+f"(c0), "+f"(c1), "+f"(c2), "+f"(c3)
                 : "r"(a0), "r"(a1), "r"(a2), "r"(a3), "r"(b0), "r"(b1));
}
// smem tile layout: [128 rows][8 granules of 16B], granule XOR-swizzled by row%8
__device__ __forceinline__ uint32_t swz(int row, int kg) {
    return (uint32_t)(row * 128 + ((kg ^ (row & 7)) << 4));
}
__device__ __forceinline__ void split2(float x, float y, uint32_t& hi, uint32_t& lo) {
    __nv_bfloat16 hx = __float2bfloat16_rn(x);
    __nv_bfloat16 hy = __float2bfloat16_rn(y);
    __nv_bfloat16 lx = __float2bfloat16_rn(x - __bfloat162float(hx));
    __nv_bfloat16 ly = __float2bfloat16_rn(y - __bfloat162float(hy));
    hi = ((uint32_t)*(uint16_t*)&hy << 16) | (uint32_t)*(uint16_t*)&hx;
    lo = ((uint32_t)*(uint16_t*)&ly << 16) | (uint32_t)*(uint16_t*)&lx;
}

// ---------------- kernel 1: obj_pts[0] vs precomputed_points ----------------
__global__ void nn1_partial(const float* __restrict__ os, const float* __restrict__ pts) {
    __shared__ float4 sP[MCHUNK];
    const int ms = blockIdx.y;
    const int m0 = ms * MCHUNK;
    for (int i = threadIdx.x; i < MCHUNK; i += 128) {
        float x = pts[(size_t)(m0 + i) * 3 + 0];
        float y = pts[(size_t)(m0 + i) * 3 + 1];
        float z = pts[(size_t)(m0 + i) * 3 + 2];
        sP[i] = make_float4(x, y, z, x * x + y * y + z * z);
    }
    __syncthreads();
    const int q0 = blockIdx.x * 256 + threadIdx.x;
    const int q1 = q0 + 128;
    const float ax = -2.0f * os[(size_t)q0 * 6 + 0];
    const float ay = -2.0f * os[(size_t)q0 * 6 + 1];
    const float az = -2.0f * os[(size_t)q0 * 6 + 2];
    const float bx = -2.0f * os[(size_t)q1 * 6 + 0];
    const float by = -2.0f * os[(size_t)q1 * 6 + 1];
    const float bz = -2.0f * os[(size_t)q1 * 6 + 2];
    float d0 = 3.4e38f, d1 = 3.4e38f;
    int i0 = 0, i1 = 0;
    #pragma unroll 5
    for (int i = 0; i < MCHUNK; i++) {
        float4 c = sP[i];
        float e0 = fmaf(ax, c.x, fmaf(ay, c.y, fmaf(az, c.z, c.w)));
        float e1 = fmaf(bx, c.x, fmaf(by, c.y, fmaf(bz, c.z, c.w)));
        if (e0 < d0) { d0 = e0; i0 = i; }
        if (e1 < d1) { d1 = e1; i1 = i; }
    }
    g_part_d[q0 * MSPLIT + ms] = d0;  g_part_i[q0 * MSPLIT + ms] = m0 + i0;
    g_part_d[q1 * MSPLIT + ms] = d1;  g_part_i[q1 * MSPLIT + ms] = m0 + i1;
}

__global__ void nn1_reduce() {
    const int q = blockIdx.x * blockDim.x + threadIdx.x;
    float best = g_part_d[q * MSPLIT];
    int bi = g_part_i[q * MSPLIT];
    #pragma unroll
    for (int s = 1; s < MSPLIT; s++) {
        float d = g_part_d[q * MSPLIT + s];
        if (d < best) { best = d; bi = g_part_i[q * MSPLIT + s]; }
    }
    g_nearest[q] = bi;
}

// ---------------- kernel 2: local/global pc vs obj_pts[p] (4 q/thread) ----------------
__global__ void match_kernel(const float* __restrict__ os,
                             const float* __restrict__ local_pc,
                             const float* __restrict__ global_pc) {
    __shared__ float4 sP[2048];
    const int p = blockIdx.y;
    const int which = blockIdx.z;
    const float* qsrc = (which == 0) ? local_pc : global_pc;
    const int tb = blockIdx.x * 1024 + threadIdx.x;
    float qx[4], qy[4], qz[4], best[4];
    int bi[4];
    #pragma unroll
    for (int u = 0; u < 4; u++) {
        const size_t qb = ((size_t)p * T_ + tb + u * 256) * 3;
        qx[u] = -2.0f * qsrc[qb + 0];
        qy[u] = -2.0f * qsrc[qb + 1];
        qz[u] = -2.0f * qsrc[qb + 2];
        best[u] = 3.4e38f;
        bi[u] = 0;
    }
    for (int nt = 0; nt < N_; nt += 2048) {
        __syncthreads();
        for (int i = threadIdx.x; i < 2048; i += 256) {
            size_t bsrc = ((size_t)p * N_ + nt + i) * 6;
            float x = os[bsrc + 0], y = os[bsrc + 1], z = os[bsrc + 2];
            sP[i] = make_float4(x, y, z, x * x + y * y + z * z);
        }
        __syncthreads();
        #pragma unroll 4
        for (int i = 0; i < 2048; i++) {
            float4 c = sP[i];
            #pragma unroll
            for (int u = 0; u < 4; u++) {
                float d = fmaf(qx[u], c.x, fmaf(qy[u], c.y, fmaf(qz[u], c.z, c.w)));
                if (d < best[u]) { best[u] = d; bi[u] = nt + i; }
            }
        }
    }
    #pragma unroll
    for (int u = 0; u < 4; u++)
        g_fidx[(size_t)which * (P_ * T_) + (size_t)p * T_ + tb + u * 256] = g_nearest[bi[u]];
}

// ---------------- kernel 3a: convert raw -> Ah/Al (k < 1024) ----------------
// grid (16384, 2), 256 threads, 4 k per thread
__global__ void convA(const float* __restrict__ geo_raw, const float* __restrict__ obj_raw) {
    const int z = blockIdx.y;
    const int m = blockIdx.x;
    const float* src = (z ? obj_raw : geo_raw) + (size_t)m * DLAT + threadIdx.x * 4;
    float4 v = *(const float4*)src;
    uint32_t h0, l0, h1, l1;
    split2(v.x, v.y, h0, l0);
    split2(v.z, v.w, h1, l1);
    size_t base = ((size_t)z * (P_ * T_) + m) * DIN + threadIdx.x * 4;
    *(uint2*)(g_Ah + base) = make_uint2(h0, h1);
    *(uint2*)(g_Al + base) = make_uint2(l0, l1);
}

// ---------------- kernel 3b: gather + convert feats -> Ah/Al (k >= 1024) ----------------
// grid (2*16384), 128 threads, 4 k per thread
__global__ void gather_conv(const float* __restrict__ pf) {
    const int row = blockIdx.x;           // z * 16384 + m
    const int fi = g_fidx[row];
    float4 v = *(const float4*)(pf + (size_t)fi * DFEAT + threadIdx.x * 4);
    uint32_t h0, l0, h1, l1;
    split2(v.x, v.y, h0, l0);
    split2(v.z, v.w, h1, l1);
    size_t base = (size_t)row * DIN + DLAT + threadIdx.x * 4;
    *(uint2*)(g_Ah + base) = make_uint2(h0, h1);
    *(uint2*)(g_Al + base) = make_uint2(l0, l1);
}

// ---------------- kernel 3c: W transpose + split -> Bh/Bl [n][k] ----------------
__global__ void convW(const float* __restrict__ Wg, const float* __restrict__ Wo) {
    __shared__ float tile[32][33];
    const int g = blockIdx.z;
    const float* W = g ? Wo : Wg;
    const int kb = blockIdx.x * 32, nb = blockIdx.y * 32;
    for (int i = threadIdx.y; i < 32; i += 8)
        tile[i][threadIdx.x] = W[(size_t)(kb + i) * DLAT + nb + threadIdx.x];
    __syncthreads();
    for (int i = threadIdx.y; i < 32; i += 8) {
        float v = tile[threadIdx.x][i];
        __nv_bfloat16 h = __float2bfloat16_rn(v);
        float l = v - __bfloat162float(h);
        size_t idx = (size_t)g * DLAT * DIN + (size_t)(nb + i) * DIN + kb + threadIdx.x;
        g_Bh[idx] = h;
        g_Bl[idx] = __float2bfloat16_rn(l);
    }
}

// ---------------- kernel 4: bf16 mma.sync GEMM with hi/lo 3-term K loop ----------------
extern __shared__ char dynsmem[];

__device__ __forceinline__ void load_stage(uint32_t sbase, int stage, int it,
                                           const __nv_bfloat16* Abase,
                                           const __nv_bfloat16* Bbase,
                                           int m0, int n0, int tid) {
    // term mapping: it<24: Ah*Bh ; 24..47: Ah*Bl ; 48..71: Al*Bh
    const int term = it / (DIN / BK);
    const int ks = (it % (DIN / BK)) * BK;
    const __nv_bfloat16* A = (term < 2) ? (g_Ah + (Abase - (__nv_bfloat16*)0 ? 0 : 0), g_Ah) : g_Al;
    // (resolved below; placeholder removed)
    (void)A;
    const __nv_bfloat16* Asrc = ((term < 2) ? g_Ah : g_Al) + (size_t)(Abase - g_Ah);
    const __nv_bfloat16* Bsrc = ((term == 1) ? g_Bl : g_Bh) + (size_t)(Bbase - g_Bh);
    uint32_t sA = sbase + stage * STAGE_BYTES;
    uint32_t sB = sA + 16384;
    #pragma unroll
    for (int p = 0; p < 4; p++) {
        int lin = p * 256 + tid;
        int row = lin >> 3, kg = lin & 7;
        cp16(sA + swz(row, kg), Asrc + (size_t)(m0 + row) * DIN + ks + kg * 8);
    }
    #pragma unroll
    for (int p = 0; p < 4; p++) {
        int lin = p * 256 + tid;
        int row = lin >> 3, kg = lin & 7;
        cp16(sB + swz(row, kg), Bsrc + (size_t)(n0 + row) * DIN + ks + kg * 8);
    }
}

__global__ void __launch_bounds__(256, 2)
gemm_mma(const float* __restrict__ bg, const float* __restrict__ bo,
         float* __restrict__ out) {
    const int z = blockIdx.z;
    const int n0 = blockIdx.x * BN;
    const int m0 = blockIdx.y * BM;
    const int tid = threadIdx.x;
    const int wid = tid >> 5;
    const int lane = tid & 31;
    const int wm = wid & 3;          // 4 warps along M (32 rows each)
    const int wn = wid >> 2;         // 2 warps along N (64 cols each)

    const __nv_bfloat16* Abase = g_Ah + (size_t)z * (P_ * T_) * DIN;  // offset carrier
    const __nv_bfloat16* Bbase = g_Bh + (size_t)z * DLAT * DIN;
    const float* bias = z ? bo : bg;
    float* C = out + (size_t)z * (P_ * T_) * DLAT;

    const uint32_t sbase = smem_u32(dynsmem);

    float acc[2][8][4];
    #pragma unroll
    for (int i = 0; i < 2; i++)
        #pragma unroll
        for (int j = 0; j < 8; j++)
            #pragma unroll
            for (int r = 0; r < 4; r++) acc[i][j][r] = 0.0f;

    // per-lane ldmatrix row/granule selectors
    const int a_row = wm * 32 + (lane & 15);
    const int a_gs  = lane >> 4;                       // 0/1
    const int b_row = wn * 64 + (lane & 7) + ((lane & 16) >> 1);
    const int b_gs  = (lane >> 3) & 1;

    // prologue: stages 0,1
    load_stage(sbase, 0, 0, Abase, Bbase, m0, n0, tid); CP_COMMIT();
    load_stage(sbase, 1, 1, Abase, Bbase, m0, n0, tid); CP_COMMIT();
    CP_WAIT(1);
    __syncthreads();

    for (int it = 0; it < NIT; it++) {
        const int s = it % NSTAGE;
        const uint32_t sA = sbase + s * STAGE_BYTES;
        const uint32_t sB = sA + 16384;
        #pragma unroll
        for (int k4 = 0; k4 < 4; k4++) {
            uint32_t a[2][4];
            #pragma unroll
            for (int mi = 0; mi < 2; mi++)
                ldmx4(sA + swz(a_row + mi * 16, k4 * 2 + a_gs),
                      a[mi][0], a[mi][1], a[mi][2], a[mi][3]);
            #pragma unroll
            for (int np = 0; np < 4; np++) {
                uint32_t b0, b1, b2, b3;
                ldmx4(sB + swz(b_row + np * 16, k4 * 2 + b_gs), b0, b1, b2, b3);
                #pragma unroll
                for (int mi = 0; mi < 2; mi++) {
                    mma16816(acc[mi][np*2][0], acc[mi][np*2][1], acc[mi][np*2][2], acc[mi][np*2][3],
                             a[mi][0], a[mi][1], a[mi][2], a[mi][3], b0, b1);
                    mma16816(acc[mi][np*2+1][0], acc[mi][np*2+1][1], acc[mi][np*2+1][2], acc[mi][np*2+1][3],
                             a[mi][0], a[mi][1], a[mi][2], a[mi][3], b2, b3);
                }
            }
        }
        __syncthreads();
        if (it + 2 < NIT)
            load_stage(sbase, (it + 2) % NSTAGE, it + 2, Abase, Bbase, m0, n0, tid);
        CP_COMMIT();
        CP_WAIT(1);
        __syncthreads();
    }

    // epilogue: bias + store
    const int row_in = lane >> 2;
    const int col_in = (lane & 3) * 2;
    #pragma unroll
    for (int np = 0; np < 8; np++) {
        const int col = n0 + wn * 64 + np * 8 + col_in;
        const float bx = __ldg(bias + col);
        const float by = __ldg(bias + col + 1);
        #pragma unroll
        for (int mi = 0; mi < 2; mi++) {
            const int r0 = m0 + wm * 32 + mi * 16 + row_in;
            float2 v0 = make_float2(acc[mi][np][0] + bx, acc[mi][np][1] + by);
            float2 v1 = make_float2(acc[mi][np][2] + bx, acc[mi][np][3] + by);
            *(float2*)(C + (size_t)r0 * DLAT + col) = v0;
            *(float2*)(C + (size_t)(r0 + 8) * DLAT + col) = v1;
        }
    }
}

// ---------------- launch ----------------
extern "C" void kernel_launch(void* const* d_in, const int* in_sizes, int n_in,
                              void* d_out, int out_size) {
    const float* object_surface = (const float*)d_in[0];
    const float* pre_pts        = (const float*)d_in[1];
    const float* pre_feats      = (const float*)d_in[2];
    const float* geo_raw        = (const float*)d_in[3];
    const float* obj_raw        = (const float*)d_in[4];
    const float* local_pc       = (const float*)d_in[5];
    const float* global_pc      = (const float*)d_in[6];
    const float* Wg             = (const float*)d_in[7];
    const float* bg             = (const float*)d_in[8];
    const float* Wo             = (const float*)d_in[9];
    const float* bo             = (const float*)d_in[10];
    float* out = (float*)d_out;

    cudaFuncSetAttribute(gemm_mma, cudaFuncAttributeMaxDynamicSharedMemorySize, GEMM_SMEM);

    convW<<<dim3(DIN / 32, DLAT / 32, 2), dim3(32, 8)>>>(Wg, Wo);
    convA<<<dim3(P_ * T_, 2), 256>>>(geo_raw, obj_raw);
    nn1_partial<<<dim3(N_ / 256, MSPLIT), 128>>>(object_surface, pre_pts);
    nn1_reduce<<<N_ / 256, 256>>>();
    match_kernel<<<dim3(T_ / 1024, P_, 2), 256>>>(object_surface, local_pc, global_pc);
    gather_conv<<<2 * P_ * T_, DFEAT / 4>>>(pre_feats);

    gemm_mma<<<dim3(DLAT / BN, (P_ * T_) / BM, 2), 256, GEMM_SMEM>>>(bg, bo, out);
}

// round 4
// speedup vs baseline: 2.8421x; 1.1808x over previous
#include <cuda_runtime.h>
#include <cuda_bf16.h>
#include <cstdint>

#define P_    8
#define T_    2048
#define N_    8192
#define M_    20000
#define DLAT  1024
#define DFEAT 512
#define DIN   1536
#define MSPLIT 8
#define MCHUNK 2500
#define NSCH  4          // match-kernel candidate chunks (8192/2048)

// ---- GEMM config: 3-term hi/lo from shared smem residency ----
#define BM 128
#define BN 256
#define BK 64                          // fp32 K per chunk
#define NCHUNK (DIN / BK)              // 24
#define SA_H 0
#define SA_L 16384
#define SB_H 32768
#define SB_L 65536
#define STAGE_BYTES 98304              // Ah16K+Al16K+Bh32K+Bl32K
#define GEMM_SMEM (2 * STAGE_BYTES)    // 192KB

// ---------------- scratch ----------------
__device__ float g_part_d[N_ * MSPLIT];
__device__ int   g_part_i[N_ * MSPLIT];
__device__ int   g_nearest[N_];
__device__ float g_mp_d[2 * P_ * NSCH * T_];
__device__ int   g_mp_i[2 * P_ * NSCH * T_];
__device__ int   g_fidx[2 * P_ * T_];
__device__ __nv_bfloat16 g_Ah[2L * P_ * T_ * DIN];
__device__ __nv_bfloat16 g_Al[2L * P_ * T_ * DIN];
__device__ __nv_bfloat16 g_Bh[2L * DLAT * DIN];
__device__ __nv_bfloat16 g_Bl[2L * DLAT * DIN];

// ---------------- helpers ----------------
__device__ __forceinline__ uint32_t smem_u32(const void* p) {
    uint32_t a;
    asm("{ .reg .u64 t; cvta.to.shared.u64 t, %1; cvt.u32.u64 %0, t; }" : "=r"(a) : "l"(p));
    return a;
}
__device__ __forceinline__ void cp16(uint32_t dst, const void* src) {
    asm volatile("cp.async.cg.shared.global [%0], [%1], 16;" :: "r"(dst), "l"(src) : "memory");
}
#define CP_COMMIT() asm volatile("cp.async.commit_group;" ::: "memory")
#define CP_WAIT0()  asm volatile("cp.async.wait_group 0;" ::: "memory")

__device__ __forceinline__ void ldmx4(uint32_t addr, uint32_t& r0, uint32_t& r1,
                                      uint32_t& r2, uint32_t& r3) {
    asm volatile("ldmatrix.sync.aligned.m8n8.x4.shared.b16 {%0,%1,%2,%3}, [%4];"
                 : "=r"(r0), "=r"(r1), "=r"(r2), "=r"(r3) : "r"(addr));
}
__device__ __forceinline__ void mma16816(float& c0, float& c1, float& c2, float& c3,
                                         uint32_t a0, uint32_t a1, uint32_t a2, uint32_t a3,
                                         uint32_t b0, uint32_t b1) {
    asm volatile("mma.sync.aligned.m16n8k16.row.col.f32.bf16.bf16.f32 "
                 "{%0,%1,%2,%3}, {%4,%5,%6,%7}, {%8,%9}, {%0,%1,%2,%3};"
                 : "+f"(c0), "+f"(c1), "+f"(c2), "+f"(c3)
                 : "r"(a0), "r"(a1), "r"(a2), "r"(a3), "r"(b0), "r"(b1));
}
__device__ __forceinline__ uint32_t swz(int row, int kg) {
    return (uint32_t)(row * 128 + ((kg ^ (row & 7)) << 4));
}
__device__ __forceinline__ void split2(float x, float y, uint32_t& hi, uint32_t& lo) {
    __nv_bfloat16 hx = __float2bfloat16_rn(x);
    __nv_bfloat16 hy = __float2bfloat16_rn(y);
    __nv_bfloat16 lx = __float2bfloat16_rn(x - __bfloat162float(hx));
    __nv_bfloat16 ly = __float2bfloat16_rn(y - __bfloat162float(hy));
    hi = ((uint32_t)*(uint16_t*)&hy << 16) | (uint32_t)*(uint16_t*)&hx;
    lo = ((uint32_t)*(uint16_t*)&ly << 16) | (uint32_t)*(uint16_t*)&lx;
}

// ---------------- kernel 1: obj_pts[0] vs precomputed_points ----------------
__global__ void nn1_partial(const float* __restrict__ os, const float* __restrict__ pts) {
    __shared__ float4 sP[MCHUNK];
    const int ms = blockIdx.y;
    const int m0 = ms * MCHUNK;
    for (int i = threadIdx.x; i < MCHUNK; i += 128) {
        float x = pts[(size_t)(m0 + i) * 3 + 0];
        float y = pts[(size_t)(m0 + i) * 3 + 1];
        float z = pts[(size_t)(m0 + i) * 3 + 2];
        sP[i] = make_float4(x, y, z, x * x + y * y + z * z);
    }
    __syncthreads();
    const int q0 = blockIdx.x * 256 + threadIdx.x;
    const int q1 = q0 + 128;
    const float ax = -2.0f * os[(size_t)q0 * 6 + 0];
    const float ay = -2.0f * os[(size_t)q0 * 6 + 1];
    const float az = -2.0f * os[(size_t)q0 * 6 + 2];
    const float bx = -2.0f * os[(size_t)q1 * 6 + 0];
    const float by = -2.0f * os[(size_t)q1 * 6 + 1];
    const float bz = -2.0f * os[(size_t)q1 * 6 + 2];
    float d0 = 3.4e38f, d1 = 3.4e38f;
    int i0 = 0, i1 = 0;
    #pragma unroll 5
    for (int i = 0; i < MCHUNK; i++) {
        float4 c = sP[i];
        float e0 = fmaf(ax, c.x, fmaf(ay, c.y, fmaf(az, c.z, c.w)));
        float e1 = fmaf(bx, c.x, fmaf(by, c.y, fmaf(bz, c.z, c.w)));
        if (e0 < d0) { d0 = e0; i0 = i; }
        if (e1 < d1) { d1 = e1; i1 = i; }
    }
    g_part_d[q0 * MSPLIT + ms] = d0;  g_part_i[q0 * MSPLIT + ms] = m0 + i0;
    g_part_d[q1 * MSPLIT + ms] = d1;  g_part_i[q1 * MSPLIT + ms] = m0 + i1;
}

__global__ void nn1_reduce() {
    const int q = blockIdx.x * blockDim.x + threadIdx.x;
    float best = g_part_d[q * MSPLIT];
    int bi = g_part_i[q * MSPLIT];
    #pragma unroll
    for (int s = 1; s < MSPLIT; s++) {
        float d = g_part_d[q * MSPLIT + s];
        if (d < best) { best = d; bi = g_part_i[q * MSPLIT + s]; }
    }
    g_nearest[q] = bi;
}

// ---------------- kernel 2: match partial (4 q/thread, 2048-candidate chunk) ----------------
// grid (T/1024, P, 2*NSCH), block 256
__global__ void match_partial(const float* __restrict__ os,
                              const float* __restrict__ local_pc,
                              const float* __restrict__ global_pc) {
    __shared__ float4 sP[2048];
    const int p = blockIdx.y;
    const int which = blockIdx.z >> 2;
    const int ch = blockIdx.z & 3;
    const int nt = ch * 2048;
    const float* qsrc = (which == 0) ? local_pc : global_pc;
    const int tb = blockIdx.x * 1024 + threadIdx.x;

    for (int i = threadIdx.x; i < 2048; i += 256) {
        size_t bsrc = ((size_t)p * N_ + nt + i) * 6;
        float x = os[bsrc + 0], y = os[bsrc + 1], z = os[bsrc + 2];
        sP[i] = make_float4(x, y, z, x * x + y * y + z * z);
    }

    float qx[4], qy[4], qz[4], best[4];
    int bi[4];
    #pragma unroll
    for (int u = 0; u < 4; u++) {
        const size_t qb = ((size_t)p * T_ + tb + u * 256) * 3;
        qx[u] = -2.0f * qsrc[qb + 0];
        qy[u] = -2.0f * qsrc[qb + 1];
        qz[u] = -2.0f * qsrc[qb + 2];
        best[u] = 3.4e38f;
        bi[u] = 0;
    }
    __syncthreads();
    #pragma unroll 4
    for (int i = 0; i < 2048; i++) {
        float4 c = sP[i];
        #pragma unroll
        for (int u = 0; u < 4; u++) {
            float d = fmaf(qx[u], c.x, fmaf(qy[u], c.y, fmaf(qz[u], c.z, c.w)));
            if (d < best[u]) { best[u] = d; bi[u] = nt + i; }
        }
    }
    #pragma unroll
    for (int u = 0; u < 4; u++) {
        size_t o = (((size_t)which * P_ + p) * NSCH + ch) * T_ + tb + u * 256;
        g_mp_d[o] = best[u];
        g_mp_i[o] = bi[u];
    }
}

// grid (2*P*T/256), 256 thr: reduce chunks ascending (first-occurrence), then nearest lookup
__global__ void match_reduce() {
    const int g = blockIdx.x * 256 + threadIdx.x;      // which*P*T + p*T + t
    const int wp = g / T_;
    const int t = g % T_;
    size_t base = ((size_t)wp * NSCH) * T_ + t;
    float best = g_mp_d[base];
    int bi = g_mp_i[base];
    #pragma unroll
    for (int c = 1; c < NSCH; c++) {
        float d = g_mp_d[base + (size_t)c * T_];
        if (d < best) { best = d; bi = g_mp_i[base + (size_t)c * T_]; }
    }
    g_fidx[g] = g_nearest[bi];
}

// ---------------- kernel 3a: raw fp32 -> Ah/Al (k < 1024) ----------------
__global__ void convA(const float* __restrict__ geo_raw, const float* __restrict__ obj_raw) {
    const int z = blockIdx.y;
    const int m = blockIdx.x;
    const float* src = (z ? obj_raw : geo_raw) + (size_t)m * DLAT + threadIdx.x * 4;
    float4 v = *(const float4*)src;
    uint32_t h0, l0, h1, l1;
    split2(v.x, v.y, h0, l0);
    split2(v.z, v.w, h1, l1);
    size_t base = ((size_t)z * (P_ * T_) + m) * DIN + threadIdx.x * 4;
    *(uint2*)(g_Ah + base) = make_uint2(h0, h1);
    *(uint2*)(g_Al + base) = make_uint2(l0, l1);
}

// ---------------- kernel 3b: gather + convert feats -> Ah/Al (k >= 1024) ----------------
__global__ void gather_conv(const float* __restrict__ pf) {
    const int row = blockIdx.x;
    const int fi = g_fidx[row];
    float4 v = *(const float4*)(pf + (size_t)fi * DFEAT + threadIdx.x * 4);
    uint32_t h0, l0, h1, l1;
    split2(v.x, v.y, h0, l0);
    split2(v.z, v.w, h1, l1);
    size_t base = (size_t)row * DIN + DLAT + threadIdx.x * 4;
    *(uint2*)(g_Ah + base) = make_uint2(h0, h1);
    *(uint2*)(g_Al + base) = make_uint2(l0, l1);
}

// ---------------- kernel 3c: W transpose + split -> Bh/Bl [n][k] ----------------
__global__ void convW(const float* __restrict__ Wg, const float* __restrict__ Wo) {
    __shared__ float tile[32][33];
    const int g = blockIdx.z;
    const float* W = g ? Wo : Wg;
    const int kb = blockIdx.x * 32, nb = blockIdx.y * 32;
    for (int i = threadIdx.y; i < 32; i += 8)
        tile[i][threadIdx.x] = W[(size_t)(kb + i) * DLAT + nb + threadIdx.x];
    __syncthreads();
    for (int i = threadIdx.y; i < 32; i += 8) {
        float v = tile[threadIdx.x][i];
        __nv_bfloat16 h = __float2bfloat16_rn(v);
        float l = v - __bfloat162float(h);
        size_t idx = (size_t)g * DLAT * DIN + (size_t)(nb + i) * DIN + kb + threadIdx.x;
        g_Bh[idx] = h;
        g_Bl[idx] = __float2bfloat16_rn(l);
    }
}

// ---------------- kernel 4: bf16 mma.sync GEMM, 3 terms per smem residency ----------------
extern __shared__ char dynsmem[];

__device__ __forceinline__ void load_chunk(uint32_t sbase, int stage, int kc,
                                           const __nv_bfloat16* Ah, const __nv_bfloat16* Al,
                                           const __nv_bfloat16* Bh, const __nv_bfloat16* Bl,
                                           int m0, int n0, int tid) {
    const int ks = kc * BK;
    const uint32_t st = sbase + stage * STAGE_BYTES;
    #pragma unroll
    for (int p = 0; p < 4; p++) {
        int lin = p * 256 + tid;
        int row = lin >> 3, kg = lin & 7;
        const size_t off = (size_t)(m0 + row) * DIN + ks + kg * 8;
        cp16(st + SA_H + swz(row, kg), Ah + off);
        cp16(st + SA_L + swz(row, kg), Al + off);
    }
    #pragma unroll
    for (int p = 0; p < 8; p++) {
        int lin = p * 256 + tid;
        int row = lin >> 3, kg = lin & 7;
        const size_t off = (size_t)(n0 + row) * DIN + ks + kg * 8;
        cp16(st + SB_H + swz(row, kg), Bh + off);
        cp16(st + SB_L + swz(row, kg), Bl + off);
    }
}

__global__ void __launch_bounds__(256, 1)
gemm_mma(const float* __restrict__ bg, const float* __restrict__ bo,
         float* __restrict__ out) {
    const int z = blockIdx.z;
    const int n0 = blockIdx.x * BN;
    const int m0 = blockIdx.y * BM;
    const int tid = threadIdx.x;
    const int wid = tid >> 5;
    const int lane = tid & 31;
    const int wm = wid & 1;          // 2 warps along M (64 rows each)
    const int wn = wid >> 1;         // 4 warps along N (64 cols each)

    const __nv_bfloat16* Ah = g_Ah + (size_t)z * (P_ * T_) * DIN;
    const __nv_bfloat16* Al = g_Al + (size_t)z * (P_ * T_) * DIN;
    const __nv_bfloat16* Bh = g_Bh + (size_t)z * DLAT * DIN;
    const __nv_bfloat16* Bl = g_Bl + (size_t)z * DLAT * DIN;
    const float* bias = z ? bo : bg;
    float* C = out + (size_t)z * (P_ * T_) * DLAT;

    const uint32_t sbase = smem_u32(dynsmem);

    float acc[4][8][4];
    #pragma unroll
    for (int i = 0; i < 4; i++)
        #pragma unroll
        for (int j = 0; j < 8; j++)
            #pragma unroll
            for (int r = 0; r < 4; r++) acc[i][j][r] = 0.0f;

    const int a_rb = wm * 64 + (lane & 15);
    const int a_gs = lane >> 4;
    const int b_rb = wn * 64 + (lane & 7) + ((lane & 16) >> 1);
    const int b_gs = (lane >> 3) & 1;

    load_chunk(sbase, 0, 0, Ah, Al, Bh, Bl, m0, n0, tid);
    CP_COMMIT();

    for (int kc = 0; kc < NCHUNK; kc++) {
        const uint32_t st = sbase + (kc & 1) * STAGE_BYTES;
        CP_WAIT0();
        __syncthreads();
        if (kc + 1 < NCHUNK) {
            load_chunk(sbase, (kc + 1) & 1, kc + 1, Ah, Al, Bh, Bl, m0, n0, tid);
            CP_COMMIT();
        }
        // 3 term passes from the same smem residency
        #pragma unroll
        for (int term = 0; term < 3; term++) {
            const uint32_t sA = st + ((term < 2) ? SA_H : SA_L);
            const uint32_t sB = st + ((term == 1) ? SB_L : SB_H);
            #pragma unroll
            for (int k4 = 0; k4 < 4; k4++) {
                uint32_t a[4][4];
                #pragma unroll
                for (int mi = 0; mi < 4; mi++)
                    ldmx4(sA + swz(a_rb + mi * 16, k4 * 2 + a_gs),
                          a[mi][0], a[mi][1], a[mi][2], a[mi][3]);
                #pragma unroll
                for (int np = 0; np < 4; np++) {
                    uint32_t b0, b1, b2, b3;
                    ldmx4(sB + swz(b_rb + np * 16, k4 * 2 + b_gs), b0, b1, b2, b3);
                    #pragma unroll
                    for (int mi = 0; mi < 4; mi++) {
                        mma16816(acc[mi][np*2][0], acc[mi][np*2][1], acc[mi][np*2][2], acc[mi][np*2][3],
                                 a[mi][0], a[mi][1], a[mi][2], a[mi][3], b0, b1);
                        mma16816(acc[mi][np*2+1][0], acc[mi][np*2+1][1], acc[mi][np*2+1][2], acc[mi][np*2+1][3],
                                 a[mi][0], a[mi][1], a[mi][2], a[mi][3], b2, b3);
                    }
                }
            }
        }
        __syncthreads();
    }

    // epilogue: bias + store
    const int row_in = lane >> 2;
    const int col_in = (lane & 3) * 2;
    #pragma unroll
    for (int np = 0; np < 8; np++) {
        const int col = n0 + wn * 64 + np * 8 + col_in;
        const float bx = __ldg(bias + col);
        const float by = __ldg(bias + col + 1);
        #pragma unroll
        for (int mi = 0; mi < 4; mi++) {
            const int r0 = m0 + wm * 64 + mi * 16 + row_in;
            *(float2*)(C + (size_t)r0 * DLAT + col) =
                make_float2(acc[mi][np][0] + bx, acc[mi][np][1] + by);
            *(float2*)(C + (size_t)(r0 + 8) * DLAT + col) =
                make_float2(acc[mi][np][2] + bx, acc[mi][np][3] + by);
        }
    }
}

// ---------------- launch ----------------
extern "C" void kernel_launch(void* const* d_in, const int* in_sizes, int n_in,
                              void* d_out, int out_size) {
    const float* object_surface = (const float*)d_in[0];
    const float* pre_pts        = (const float*)d_in[1];
    const float* pre_feats      = (const float*)d_in[2];
    const float* geo_raw        = (const float*)d_in[3];
    const float* obj_raw        = (const float*)d_in[4];
    const float* local_pc       = (const float*)d_in[5];
    const float* global_pc      = (const float*)d_in[6];
    const float* Wg             = (const float*)d_in[7];
    const float* bg             = (const float*)d_in[8];
    const float* Wo             = (const float*)d_in[9];
    const float* bo             = (const float*)d_in[10];
    float* out = (float*)d_out;

    cudaFuncSetAttribute(gemm_mma, cudaFuncAttributeMaxDynamicSharedMemorySize, GEMM_SMEM);

    convW<<<dim3(DIN / 32, DLAT / 32, 2), dim3(32, 8)>>>(Wg, Wo);
    convA<<<dim3(P_ * T_, 2), 256>>>(geo_raw, obj_raw);
    nn1_partial<<<dim3(N_ / 256, MSPLIT), 128>>>(object_surface, pre_pts);
    nn1_reduce<<<N_ / 256, 256>>>();
    match_partial<<<dim3(T_ / 1024, P_, 2 * NSCH), 256>>>(object_surface, local_pc, global_pc);
    match_reduce<<<2 * P_ * T_ / 256, 256>>>();
    gather_conv<<<2 * P_ * T_, DFEAT / 4>>>(pre_feats);

    gemm_mma<<<dim3(DLAT / BN, (P_ * T_) / BM, 2), 256, GEMM_SMEM>>>(bg, bo, out);
}

// round 5
// speedup vs baseline: 5.8261x; 2.0499x over previous
#include <cuda_runtime.h>
#include <cuda_fp16.h>
#include <cstdint>

#define P_    8
#define T_    2048
#define N_    8192
#define M_    20000
#define DLAT  1024
#define DFEAT 512
#define DIN   1536
#define MSPLIT 8
#define MCHUNK 2500
#define NSCH  4

// ---- GEMM config: single-term fp16, fp32 accumulate ----
#define BM 128
#define BN 128
#define BK 64                          // k per chunk
#define NCHUNK (DIN / BK)              // 24
#define NSTG 3
#define STG_BYTES 32768                // A 16K + B 16K
#define GEMM_SMEM (NSTG * STG_BYTES)   // 96KB

// ---------------- scratch ----------------
__device__ float g_part_d[N_ * MSPLIT];
__device__ int   g_part_i[N_ * MSPLIT];
__device__ int   g_nearest[N_];
__device__ float g_mp_d[2 * P_ * NSCH * T_];
__device__ int   g_mp_i[2 * P_ * NSCH * T_];
__device__ int   g_fidx[2 * P_ * T_];
__device__ __half g_A[2L * P_ * T_ * DIN];    // [gemm][m][k] fp16
__device__ __half g_B[2L * DLAT * DIN];       // [gemm][n][k] fp16 (W^T)

// ---------------- helpers ----------------
__device__ __forceinline__ uint32_t smem_u32(const void* p) {
    uint32_t a;
    asm("{ .reg .u64 t; cvta.to.shared.u64 t, %1; cvt.u32.u64 %0, t; }" : "=r"(a) : "l"(p));
    return a;
}
__device__ __forceinline__ void cp16(uint32_t dst, const void* src) {
    asm volatile("cp.async.cg.shared.global [%0], [%1], 16;" :: "r"(dst), "l"(src) : "memory");
}
#define CP_COMMIT() asm volatile("cp.async.commit_group;" ::: "memory")
#define CP_WAIT1()  asm volatile("cp.async.wait_group 1;" ::: "memory")

__device__ __forceinline__ void ldmx4(uint32_t addr, uint32_t& r0, uint32_t& r1,
                                      uint32_t& r2, uint32_t& r3) {
    asm volatile("ldmatrix.sync.aligned.m8n8.x4.shared.b16 {%0,%1,%2,%3}, [%4];"
                 : "=r"(r0), "=r"(r1), "=r"(r2), "=r"(r3) : "r"(addr));
}
__device__ __forceinline__ void mma16816(float& c0, float& c1, float& c2, float& c3,
                                         uint32_t a0, uint32_t a1, uint32_t a2, uint32_t a3,
                                         uint32_t b0, uint32_t b1) {
    asm volatile("mma.sync.aligned.m16n8k16.row.col.f32.f16.f16.f32 "
                 "{%0,%1,%2,%3}, {%4,%5,%6,%7}, {%8,%9}, {%0,%1,%2,%3};"
                 : "+f"(c0), "+f"(c1), "+f"(c2), "+f"(c3)
                 : "r"(a0), "r"(a1), "r"(a2), "r"(a3), "r"(b0), "r"(b1));
}
__device__ __forceinline__ uint32_t swz(int row, int kg) {
    return (uint32_t)(row * 128 + ((kg ^ (row & 7)) << 4));
}
__device__ __forceinline__ uint2 pack4h(float4 v) {
    __half hx = __float2half_rn(v.x), hy = __float2half_rn(v.y);
    __half hz = __float2half_rn(v.z), hw = __float2half_rn(v.w);
    uint2 r;
    r.x = ((uint32_t)*(uint16_t*)&hy << 16) | (uint32_t)*(uint16_t*)&hx;
    r.y = ((uint32_t)*(uint16_t*)&hw << 16) | (uint32_t)*(uint16_t*)&hz;
    return r;
}

// ---------------- kernel 1: obj_pts[0] vs precomputed_points ----------------
__global__ void nn1_partial(const float* __restrict__ os, const float* __restrict__ pts) {
    __shared__ float4 sP[MCHUNK];
    const int ms = blockIdx.y;
    const int m0 = ms * MCHUNK;
    for (int i = threadIdx.x; i < MCHUNK; i += 128) {
        float x = pts[(size_t)(m0 + i) * 3 + 0];
        float y = pts[(size_t)(m0 + i) * 3 + 1];
        float z = pts[(size_t)(m0 + i) * 3 + 2];
        sP[i] = make_float4(x, y, z, x * x + y * y + z * z);
    }
    __syncthreads();
    const int q0 = blockIdx.x * 256 + threadIdx.x;
    const int q1 = q0 + 128;
    const float ax = -2.0f * os[(size_t)q0 * 6 + 0];
    const float ay = -2.0f * os[(size_t)q0 * 6 + 1];
    const float az = -2.0f * os[(size_t)q0 * 6 + 2];
    const float bx = -2.0f * os[(size_t)q1 * 6 + 0];
    const float by = -2.0f * os[(size_t)q1 * 6 + 1];
    const float bz = -2.0f * os[(size_t)q1 * 6 + 2];
    float d0 = 3.4e38f, d1 = 3.4e38f;
    int i0 = 0, i1 = 0;
    #pragma unroll 5
    for (int i = 0; i < MCHUNK; i++) {
        float4 c = sP[i];
        float e0 = fmaf(ax, c.x, fmaf(ay, c.y, fmaf(az, c.z, c.w)));
        float e1 = fmaf(bx, c.x, fmaf(by, c.y, fmaf(bz, c.z, c.w)));
        if (e0 < d0) { d0 = e0; i0 = i; }
        if (e1 < d1) { d1 = e1; i1 = i; }
    }
    g_part_d[q0 * MSPLIT + ms] = d0;  g_part_i[q0 * MSPLIT + ms] = m0 + i0;
    g_part_d[q1 * MSPLIT + ms] = d1;  g_part_i[q1 * MSPLIT + ms] = m0 + i1;
}

__global__ void nn1_reduce() {
    const int q = blockIdx.x * blockDim.x + threadIdx.x;
    float best = g_part_d[q * MSPLIT];
    int bi = g_part_i[q * MSPLIT];
    #pragma unroll
    for (int s = 1; s < MSPLIT; s++) {
        float d = g_part_d[q * MSPLIT + s];
        if (d < best) { best = d; bi = g_part_i[q * MSPLIT + s]; }
    }
    g_nearest[q] = bi;
}

// ---------------- kernel 2: match partial + reduce ----------------
__global__ void match_partial(const float* __restrict__ os,
                              const float* __restrict__ local_pc,
                              const float* __restrict__ global_pc) {
    __shared__ float4 sP[2048];
    const int p = blockIdx.y;
    const int which = blockIdx.z >> 2;
    const int ch = blockIdx.z & 3;
    const int nt = ch * 2048;
    const float* qsrc = (which == 0) ? local_pc : global_pc;
    const int tb = blockIdx.x * 1024 + threadIdx.x;

    for (int i = threadIdx.x; i < 2048; i += 256) {
        size_t bsrc = ((size_t)p * N_ + nt + i) * 6;
        float x = os[bsrc + 0], y = os[bsrc + 1], z = os[bsrc + 2];
        sP[i] = make_float4(x, y, z, x * x + y * y + z * z);
    }

    float qx[4], qy[4], qz[4], best[4];
    int bi[4];
    #pragma unroll
    for (int u = 0; u < 4; u++) {
        const size_t qb = ((size_t)p * T_ + tb + u * 256) * 3;
        qx[u] = -2.0f * qsrc[qb + 0];
        qy[u] = -2.0f * qsrc[qb + 1];
        qz[u] = -2.0f * qsrc[qb + 2];
        best[u] = 3.4e38f;
        bi[u] = 0;
    }
    __syncthreads();
    #pragma unroll 4
    for (int i = 0; i < 2048; i++) {
        float4 c = sP[i];
        #pragma unroll
        for (int u = 0; u < 4; u++) {
            float d = fmaf(qx[u], c.x, fmaf(qy[u], c.y, fmaf(qz[u], c.z, c.w)));
            if (d < best[u]) { best[u] = d; bi[u] = nt + i; }
        }
    }
    #pragma unroll
    for (int u = 0; u < 4; u++) {
        size_t o = (((size_t)which * P_ + p) * NSCH + ch) * T_ + tb + u * 256;
        g_mp_d[o] = best[u];
        g_mp_i[o] = bi[u];
    }
}

__global__ void match_reduce() {
    const int g = blockIdx.x * 256 + threadIdx.x;
    const int wp = g / T_;
    const int t = g % T_;
    size_t base = ((size_t)wp * NSCH) * T_ + t;
    float best = g_mp_d[base];
    int bi = g_mp_i[base];
    #pragma unroll
    for (int c = 1; c < NSCH; c++) {
        float d = g_mp_d[base + (size_t)c * T_];
        if (d < best) { best = d; bi = g_mp_i[base + (size_t)c * T_]; }
    }
    g_fidx[g] = g_nearest[bi];
}

// ---------------- kernel 3a: raw fp32 -> fp16 (k < 1024) ----------------
__global__ void convA(const float* __restrict__ geo_raw, const float* __restrict__ obj_raw) {
    const int z = blockIdx.y;
    const int m = blockIdx.x;
    const float* src = (z ? obj_raw : geo_raw) + (size_t)m * DLAT + threadIdx.x * 4;
    float4 v = *(const float4*)src;
    size_t base = ((size_t)z * (P_ * T_) + m) * DIN + threadIdx.x * 4;
    *(uint2*)(g_A + base) = pack4h(v);
}

// ---------------- kernel 3b: gather + convert feats -> fp16 (k >= 1024) ----------------
__global__ void gather_conv(const float* __restrict__ pf) {
    const int row = blockIdx.x;
    const int fi = g_fidx[row];
    float4 v = *(const float4*)(pf + (size_t)fi * DFEAT + threadIdx.x * 4);
    size_t base = (size_t)row * DIN + DLAT + threadIdx.x * 4;
    *(uint2*)(g_A + base) = pack4h(v);
}

// ---------------- kernel 3c: W transpose -> fp16 [n][k] ----------------
__global__ void convW(const float* __restrict__ Wg, const float* __restrict__ Wo) {
    __shared__ float tile[32][33];
    const int g = blockIdx.z;
    const float* W = g ? Wo : Wg;
    const int kb = blockIdx.x * 32, nb = blockIdx.y * 32;
    for (int i = threadIdx.y; i < 32; i += 8)
        tile[i][threadIdx.x] = W[(size_t)(kb + i) * DLAT + nb + threadIdx.x];
    __syncthreads();
    for (int i = threadIdx.y; i < 32; i += 8) {
        float v = tile[threadIdx.x][i];
        size_t idx = (size_t)g * DLAT * DIN + (size_t)(nb + i) * DIN + kb + threadIdx.x;
        g_B[idx] = __float2half_rn(v);
    }
}

// ---------------- kernel 4: fp16 mma.sync GEMM ----------------
extern __shared__ char dynsmem[];

__device__ __forceinline__ void load_chunk(uint32_t sbase, int stage, int kc,
                                           const __half* A, const __half* B,
                                           int m0, int n0, int tid) {
    const int ks = kc * BK;
    const uint32_t st = sbase + stage * STG_BYTES;
    #pragma unroll
    for (int p = 0; p < 4; p++) {
        int lin = p * 256 + tid;
        int row = lin >> 3, kg = lin & 7;
        cp16(st + swz(row, kg), A + (size_t)(m0 + row) * DIN + ks + kg * 8);
    }
    #pragma unroll
    for (int p = 0; p < 4; p++) {
        int lin = p * 256 + tid;
        int row = lin >> 3, kg = lin & 7;
        cp16(st + 16384 + swz(row, kg), B + (size_t)(n0 + row) * DIN + ks + kg * 8);
    }
}

__global__ void __launch_bounds__(256, 2)
gemm_mma(const float* __restrict__ bg, const float* __restrict__ bo,
         float* __restrict__ out) {
    const int z = blockIdx.z;
    const int n0 = blockIdx.x * BN;
    const int m0 = blockIdx.y * BM;
    const int tid = threadIdx.x;
    const int wid = tid >> 5;
    const int lane = tid & 31;
    const int wm = wid & 1;          // 2 warps along M (64 rows)
    const int wn = wid >> 1;         // 4 warps along N (32 cols)

    const __half* A = g_A + (size_t)z * (P_ * T_) * DIN;
    const __half* B = g_B + (size_t)z * DLAT * DIN;
    const float* bias = z ? bo : bg;
    float* C = out + (size_t)z * (P_ * T_) * DLAT;

    const uint32_t sbase = smem_u32(dynsmem);

    float acc[4][4][4];
    #pragma unroll
    for (int i = 0; i < 4; i++)
        #pragma unroll
        for (int j = 0; j < 4; j++)
            #pragma unroll
            for (int r = 0; r < 4; r++) acc[i][j][r] = 0.0f;

    const int a_rb = wm * 64 + (lane & 15);
    const int a_gs = lane >> 4;
    const int b_rb = wn * 32 + (lane & 7) + ((lane & 16) >> 1);
    const int b_gs = (lane >> 3) & 1;

    load_chunk(sbase, 0, 0, A, B, m0, n0, tid); CP_COMMIT();
    load_chunk(sbase, 1, 1, A, B, m0, n0, tid); CP_COMMIT();

    for (int kc = 0; kc < NCHUNK; kc++) {
        CP_WAIT1();
        __syncthreads();
        if (kc + 2 < NCHUNK)
            load_chunk(sbase, (kc + 2) % NSTG, kc + 2, A, B, m0, n0, tid);
        CP_COMMIT();

        const uint32_t sA = sbase + (kc % NSTG) * STG_BYTES;
        const uint32_t sB = sA + 16384;
        #pragma unroll
        for (int k4 = 0; k4 < 4; k4++) {
            uint32_t a[4][4];
            #pragma unroll
            for (int mi = 0; mi < 4; mi++)
                ldmx4(sA + swz(a_rb + mi * 16, k4 * 2 + a_gs),
                      a[mi][0], a[mi][1], a[mi][2], a[mi][3]);
            #pragma unroll
            for (int npp = 0; npp < 2; npp++) {
                uint32_t b0, b1, b2, b3;
                ldmx4(sB + swz(b_rb + npp * 16, k4 * 2 + b_gs), b0, b1, b2, b3);
                #pragma unroll
                for (int mi = 0; mi < 4; mi++) {
                    mma16816(acc[mi][npp*2][0], acc[mi][npp*2][1], acc[mi][npp*2][2], acc[mi][npp*2][3],
                             a[mi][0], a[mi][1], a[mi][2], a[mi][3], b0, b1);
                    mma16816(acc[mi][npp*2+1][0], acc[mi][npp*2+1][1], acc[mi][npp*2+1][2], acc[mi][npp*2+1][3],
                             a[mi][0], a[mi][1], a[mi][2], a[mi][3], b2, b3);
                }
            }
        }
    }

    // epilogue: bias + store
    const int row_in = lane >> 2;
    const int col_in = (lane & 3) * 2;
    #pragma unroll
    for (int np = 0; np < 4; np++) {
        const int col = n0 + wn * 32 + np * 8 + col_in;
        const float bx = __ldg(bias + col);
        const float by = __ldg(bias + col + 1);
        #pragma unroll
        for (int mi = 0; mi < 4; mi++) {
            const int r0 = m0 + wm * 64 + mi * 16 + row_in;
            *(float2*)(C + (size_t)r0 * DLAT + col) =
                make_float2(acc[mi][np][0] + bx, acc[mi][np][1] + by);
            *(float2*)(C + (size_t)(r0 + 8) * DLAT + col) =
                make_float2(acc[mi][np][2] + bx, acc[mi][np][3] + by);
        }
    }
}

// ---------------- launch ----------------
extern "C" void kernel_launch(void* const* d_in, const int* in_sizes, int n_in,
                              void* d_out, int out_size) {
    const float* object_surface = (const float*)d_in[0];
    const float* pre_pts        = (const float*)d_in[1];
    const float* pre_feats      = (const float*)d_in[2];
    const float* geo_raw        = (const float*)d_in[3];
    const float* obj_raw        = (const float*)d_in[4];
    const float* local_pc       = (const float*)d_in[5];
    const float* global_pc      = (const float*)d_in[6];
    const float* Wg             = (const float*)d_in[7];
    const float* bg             = (const float*)d_in[8];
    const float* Wo             = (const float*)d_in[9];
    const float* bo             = (const float*)d_in[10];
    float* out = (float*)d_out;

    cudaFuncSetAttribute(gemm_mma, cudaFuncAttributeMaxDynamicSharedMemorySize, GEMM_SMEM);

    convW<<<dim3(DIN / 32, DLAT / 32, 2), dim3(32, 8)>>>(Wg, Wo);
    convA<<<dim3(P_ * T_, 2), 256>>>(geo_raw, obj_raw);
    nn1_partial<<<dim3(N_ / 256, MSPLIT), 128>>>(object_surface, pre_pts);
    nn1_reduce<<<N_ / 256, 256>>>();
    match_partial<<<dim3(T_ / 1024, P_, 2 * NSCH), 256>>>(object_surface, local_pc, global_pc);
    match_reduce<<<2 * P_ * T_ / 256, 256>>>();
    gather_conv<<<2 * P_ * T_, DFEAT / 4>>>(pre_feats);

    gemm_mma<<<dim3(DLAT / BN, (P_ * T_) / BM, 2), 256, GEMM_SMEM>>>(bg, bo, out);
}